// round 1
// baseline (speedup 1.0000x reference)
#include <cuda_runtime.h>
#include <math.h>

#define TW 32
#define TH 8
#define NT 256
#define IMW 512
#define IMH 512
#define NCH 12
#define NBINS 256

// SMEM weight layout (per predictor), rows padded to 16B multiples for LDS.128:
//  w0:  32 rows of [24 taps weights, bias] stride 28
//  wA:  32 rows of [32 w1, b1] stride 36
//  wB:  32 rows of [32 w2, b2] stride 36
//  wC:  [32 w3, b3] (36)
#define W0_STRIDE 28
#define WA_OFF (32 * W0_STRIDE)              // 896
#define WAB_STRIDE 36
#define WB_OFF (WA_OFF + 32 * WAB_STRIDE)    // 2048
#define WC_OFF (WB_OFF + 32 * WAB_STRIDE)    // 3200
#define PRED_STRIDE (WC_OFF + 36)            // 3236 floats

struct Params { const float* p[27]; };

__device__ double g_sumsq[2];                    // [0]=x, [1]=delta
__device__ unsigned int g_hist[2][NCH][NBINS];   // [0]=x, [1]=delta

__global__ void zero_kernel() {
    int i = blockIdx.x * blockDim.x + threadIdx.x;
    if (i < 2) g_sumsq[i] = 0.0;
    if (i < 2 * NCH * NBINS) ((unsigned int*)g_hist)[i] = 0u;
}

__device__ __forceinline__ float leaky(float v) { return fmaxf(v, 0.01f * v); }

__global__ __launch_bounds__(NT) void predict_kernel(const float* __restrict__ x, Params prm) {
    __shared__ float s_tile[TH + 3][TW + 8];      // 11 x 38 used
    __shared__ float s_w[3 * PRED_STRIDE];        // ~38.8 KB
    __shared__ unsigned int s_hist[2][NBINS];
    __shared__ double s_red[2][NT / 32];

    const int tx = threadIdx.x, ty = threadIdx.y;
    const int tid = ty * TW + tx;
    const int ch  = blockIdx.z;
    const int gx0 = blockIdx.x * TW;
    const int gy0 = blockIdx.y * TH;

    // zero shared hist
    for (int i = tid; i < 2 * NBINS; i += NT) ((unsigned int*)s_hist)[i] = 0u;

    // stage weights into padded SMEM layout
    for (int p = 0; p < 3; ++p) {
        const float* wT = prm.p[p * 9 + 0];
        const float* bT = prm.p[p * 9 + 1];
        const float* wL = prm.p[p * 9 + 2];
        const float* w1 = prm.p[p * 9 + 3];
        const float* b1 = prm.p[p * 9 + 4];
        const float* w2 = prm.p[p * 9 + 5];
        const float* b2 = prm.p[p * 9 + 6];
        const float* w3 = prm.p[p * 9 + 7];
        const float* b3 = prm.p[p * 9 + 8];
        float* base = s_w + p * PRED_STRIDE;
        for (int i = tid; i < 32 * 21; i += NT) base[(i / 21) * W0_STRIDE + (i % 21)] = wT[i];
        for (int i = tid; i < 32 * 3;  i += NT) base[(i / 3) * W0_STRIDE + 21 + (i % 3)] = wL[i];
        for (int i = tid; i < 32;      i += NT) base[i * W0_STRIDE + 24] = bT[i];
        for (int i = tid; i < 32 * 32; i += NT) base[WA_OFF + (i / 32) * WAB_STRIDE + (i % 32)] = w1[i];
        for (int i = tid; i < 32;      i += NT) base[WA_OFF + i * WAB_STRIDE + 32] = b1[i];
        for (int i = tid; i < 32 * 32; i += NT) base[WB_OFF + (i / 32) * WAB_STRIDE + (i % 32)] = w2[i];
        for (int i = tid; i < 32;      i += NT) base[WB_OFF + i * WAB_STRIDE + 32] = b2[i];
        for (int i = tid; i < 32;      i += NT) base[WC_OFF + i] = w3[i];
        if (tid == 0) base[WC_OFF + 32] = b3[0];
    }

    // stage input tile with halo (top 3 rows, left 3 / right 3 cols), zero-padded
    const float* xch = x + (size_t)ch * IMH * IMW;
    for (int i = tid; i < (TH + 3) * (TW + 6); i += NT) {
        int r = i / (TW + 6), c = i % (TW + 6);
        int gr = gy0 - 3 + r, gc = gx0 - 3 + c;
        float v = 0.f;
        if (gr >= 0 && gc >= 0 && gc < IMW) v = xch[gr * IMW + gc];
        s_tile[r][c] = v;
    }
    __syncthreads();

    // gather 24 causal taps into registers:
    // top context: rows i-3..i-1, cols j-3..j+3 ; left context: row i, cols j-3..j-1
    float t[24];
#pragma unroll
    for (int di = 0; di < 3; ++di)
#pragma unroll
        for (int dj = 0; dj < 7; ++dj)
            t[di * 7 + dj] = s_tile[ty + di][tx + dj];
#pragma unroll
    for (int dj = 0; dj < 3; ++dj)
        t[21 + dj] = s_tile[ty + 3][tx + dj];

    float preds[3];
#pragma unroll 1
    for (int p = 0; p < 3; ++p) {
        const float* wb = s_w + p * PRED_STRIDE;
        float h1[32], h2[32];
#pragma unroll
        for (int oc = 0; oc < 32; ++oc) {
            const float* w = wb + oc * W0_STRIDE;
            float a = w[24];
#pragma unroll
            for (int k = 0; k < 24; ++k) a = fmaf(w[k], t[k], a);
            h1[oc] = leaky(a);
        }
#pragma unroll
        for (int oc = 0; oc < 32; ++oc) {
            const float* w = wb + WA_OFF + oc * WAB_STRIDE;
            float a = w[32];
#pragma unroll
            for (int k = 0; k < 32; ++k) a = fmaf(w[k], h1[k], a);
            h2[oc] = leaky(a);
        }
#pragma unroll
        for (int oc = 0; oc < 32; ++oc) {
            const float* w = wb + WB_OFF + oc * WAB_STRIDE;
            float a = w[32];
#pragma unroll
            for (int k = 0; k < 32; ++k) a = fmaf(w[k], h2[k], a);
            h1[oc] = leaky(a);   // reuse as h3
        }
        {
            const float* w = wb + WC_OFF;
            float a = w[32];
#pragma unroll
            for (int k = 0; k < 32; ++k) a = fmaf(w[k], h1[k], a);
            preds[p] = fminf(fmaxf(a, -1.f), 1.f);
        }
    }

    const float x0 = s_tile[ty + 3][tx + 3];
    const float pa = preds[0], pb = preds[1], pc = preds[2];
    const float med = fmaxf(fminf(pa, fmaxf(pb, pc)), fminf(pb, pc));
    const float delta = fmodf(x0 - med + 1.0f, 2.0f) - 1.0f;

    // per-channel histograms via shared atomics (mask: only values in [-1,1] counted)
    if (x0 >= -1.f && x0 <= 1.f) {
        int idx = (int)floorf((x0 + 1.f) * 128.f);
        idx = min(max(idx, 0), NBINS - 1);
        atomicAdd(&s_hist[0][idx], 1u);
    }
    if (delta >= -1.f && delta <= 1.f) {
        int idx = (int)floorf((delta + 1.f) * 128.f);
        idx = min(max(idx, 0), NBINS - 1);
        atomicAdd(&s_hist[1][idx], 1u);
    }

    // sum-of-squares block reduction (double)
    double vx = (double)x0 * (double)x0;
    double vd = (double)delta * (double)delta;
#pragma unroll
    for (int o = 16; o > 0; o >>= 1) {
        vx += __shfl_down_sync(0xffffffffu, vx, o);
        vd += __shfl_down_sync(0xffffffffu, vd, o);
    }
    const int warp = tid >> 5, lane = tid & 31;
    if (lane == 0) { s_red[0][warp] = vx; s_red[1][warp] = vd; }
    __syncthreads();
    if (tid == 0) {
        double sx = 0.0, sd = 0.0;
#pragma unroll
        for (int i = 0; i < NT / 32; ++i) { sx += s_red[0][i]; sd += s_red[1][i]; }
        atomicAdd(&g_sumsq[0], sx);
        atomicAdd(&g_sumsq[1], sd);
    }
    if (tid < NBINS) {
        unsigned c0 = s_hist[0][tid], c1 = s_hist[1][tid];
        if (c0) atomicAdd(&g_hist[0][ch][tid], c0);
        if (c1) atomicAdd(&g_hist[1][ch][tid], c1);
    }
}

__global__ void finalize_kernel(float* out) {
    __shared__ double s_ent[2][8];
    const int tid = threadIdx.x;
    double e0 = 0.0, e1 = 0.0;
    const double res = (double)(IMH * IMW);
    for (int i = tid; i < NCH * NBINS; i += 256) {
        unsigned c0 = ((const unsigned*)g_hist[0])[i];
        unsigned c1 = ((const unsigned*)g_hist[1])[i];
        if (c0) { double pp = (double)c0 / res; e0 -= pp * log2(pp); }
        if (c1) { double pp = (double)c1 / res; e1 -= pp * log2(pp); }
    }
#pragma unroll
    for (int o = 16; o > 0; o >>= 1) {
        e0 += __shfl_down_sync(0xffffffffu, e0, o);
        e1 += __shfl_down_sync(0xffffffffu, e1, o);
    }
    if ((tid & 31) == 0) { s_ent[0][tid >> 5] = e0; s_ent[1][tid >> 5] = e1; }
    __syncthreads();
    if (tid == 0) {
        double E0 = 0.0, E1 = 0.0;
#pragma unroll
        for (int i = 0; i < 8; ++i) { E0 += s_ent[0][i]; E1 += s_ent[1][i]; }
        const double N = (double)NCH * IMH * IMW;
        out[0] = (float)(255.0 * sqrt(g_sumsq[1] / N));   // loss1
        out[1] = (float)(255.0 * sqrt(g_sumsq[0] / N));   // loss0
        out[2] = (float)(E0 / (8.0 * NCH));               // invCR0
        out[3] = (float)(E1 / (8.0 * NCH));               // invCR1
    }
}

extern "C" void kernel_launch(void* const* d_in, const int* in_sizes, int n_in,
                              void* d_out, int out_size) {
    const float* x = (const float*)d_in[0];
    Params prm;
    for (int i = 0; i < 27; ++i) prm.p[i] = (const float*)d_in[1 + i];

    zero_kernel<<<24, 256>>>();
    dim3 grid(IMW / TW, IMH / TH, NCH);
    dim3 block(TW, TH);
    predict_kernel<<<grid, block>>>(x, prm);
    finalize_kernel<<<1, 256>>>((float*)d_out);
}